// round 8
// baseline (speedup 1.0000x reference)
#include <cuda_runtime.h>

#define H 256
#define P_PATHS 32768
#define LMAX 16
#define KDIM 288          // 256 path_emb + 8 edge + 16 scalar + 8 zero pad
#define NSTAGES 36        // KDIM / 8
#define MTILE 64          // paths per tile
#define NT (P_PATHS / MTILE)   // 512 tiles
#define GRID 148
#define THREADS 512

// ---------------- persistent scratch (no allocations allowed) ----------------
__device__ __align__(128) float g_Wf[KDIM * H];     // packed W1 tail (k-major, zero-padded)
__device__ __align__(128) float g_cpart[8][H];      // partial src/dst + b1 contribution
__device__ int g_ticket;                            // dynamic tile ticket

// ---------------- packed f32x2 helpers (sm_103a FFMA2 path) ----------------
typedef unsigned long long u64;
__device__ __forceinline__ u64 pack2(float x, float y) {
    u64 r; asm("mov.b64 %0, {%1, %2};" : "=l"(r) : "f"(x), "f"(y)); return r;
}
__device__ __forceinline__ void unpack2(u64 v, float& x, float& y) {
    asm("mov.b64 {%0, %1}, %2;" : "=f"(x), "=f"(y) : "l"(v));
}
__device__ __forceinline__ void ffma2(u64& d, u64 a, u64 b) {
    asm("fma.rn.f32x2 %0, %1, %2, %0;" : "+l"(d) : "l"(a), "l"(b));
}

// bank swizzle for the k-major A tile: permutes 4-column groups per 8-k block
__device__ __forceinline__ int swz(int k) { return ((k >> 3) & 7) << 2; }

// ---------------- kernel 1: prep = pack Wf + compute c partials + ticket reset ----------------
// fused layout: [src 0:256 | dst 256:512 | path_emb 512:768 | edge 768:776 | scalar 776:792]
__global__ void prep_kernel(const float* __restrict__ W1,
                            const float* __restrict__ node_embs,
                            const float* __restrict__ b1,
                            const int* __restrict__ src_idx,
                            const int* __restrict__ dst_idx) {
    int bid = blockIdx.x;
    int j = threadIdx.x;     // 0..255
    if (bid == 0 && j == 0) g_ticket = GRID;   // first GRID tiles are static
    if (bid < KDIM) {
        int k = bid;
        float v = 0.f;
        if (k < 256)       v = W1[(512 + k) * H + j];
        else if (k < 264)  v = W1[(768 + (k - 256)) * H + j];
        else if (k < 280)  v = W1[(776 + (k - 264)) * H + j];
        g_Wf[k * H + j] = v;
    } else {
        int b = bid - KDIM;  // 0..7 : k slice [b*32, b*32+32)
        const float* s = node_embs + (long)(*src_idx) * H;
        const float* d = node_embs + (long)(*dst_idx) * H;
        float acc = (b == 0) ? b1[j] : 0.f;
        int k0 = b * 32;
#pragma unroll 8
        for (int k = k0; k < k0 + 32; k++) {
            acc = fmaf(s[k], W1[k * H + j], acc);
            acc = fmaf(d[k], W1[(256 + k) * H + j], acc);
        }
        g_cpart[b][j] = acc;
    }
}

// ---------------- gather helpers ----------------
// One full path mean, warp-collective: lane holds k = [4*lane,4*lane+4) and [128+4*lane, ...)
__device__ __forceinline__ void gather_path(float* __restrict__ Asw,
                                            const float* __restrict__ node_embs,
                                            const int* __restrict__ path_nodes,
                                            const int* __restrict__ path_lens,
                                            int p, int pl, int lane) {
    int len = path_lens[p];
    const int4* nb = (const int4*)(path_nodes + (size_t)p * LMAX);
    int4 q0 = nb[0], q1 = nb[1], q2 = nb[2], q3 = nb[3];
    int ids[16] = {q0.x, q0.y, q0.z, q0.w, q1.x, q1.y, q1.z, q1.w,
                   q2.x, q2.y, q2.z, q2.w, q3.x, q3.y, q3.z, q3.w};
    float4 a0 = make_float4(0.f, 0.f, 0.f, 0.f);
    float4 a1 = make_float4(0.f, 0.f, 0.f, 0.f);
#pragma unroll
    for (int l = 0; l < LMAX; l++) {
        if (l < len) {
            const float4* r = (const float4*)(node_embs + (size_t)ids[l] * H);
            float4 v0 = r[lane];
            float4 v1 = r[32 + lane];
            a0.x += v0.x; a0.y += v0.y; a0.z += v0.z; a0.w += v0.w;
            a1.x += v1.x; a1.y += v1.y; a1.z += v1.z; a1.w += v1.w;
        }
    }
    float inv = 1.f / (float)max(len, 1);
    int k0 = 4 * lane;
    float va0[4] = {a0.x, a0.y, a0.z, a0.w};
    float va1[4] = {a1.x, a1.y, a1.z, a1.w};
#pragma unroll
    for (int j = 0; j < 4; j++) {
        int ka = k0 + j, kb = 128 + k0 + j;
        Asw[ka * MTILE + (pl ^ swz(ka))] = va0[j] * inv;
        Asw[kb * MTILE + (pl ^ swz(kb))] = va1[j] * inv;
    }
}

// edge + scalar rows (k = 256..279) for one path, one thread
__device__ __forceinline__ void edge_rows(float* __restrict__ Asw,
                                          const float* __restrict__ edge_feats,
                                          const float* __restrict__ scalar_feats,
                                          int p, int pl) {
    const float4* ef = (const float4*)(edge_feats + (size_t)p * 8);
    float4 e0 = ef[0], e1 = ef[1];
    const float4* sf = (const float4*)(scalar_feats + (size_t)p * 16);
    float4 s0 = sf[0], s1 = sf[1], s2 = sf[2], s3 = sf[3];
    float ev[8]  = {e0.x, e0.y, e0.z, e0.w, e1.x, e1.y, e1.z, e1.w};
    float sv[16] = {s0.x, s0.y, s0.z, s0.w, s1.x, s1.y, s1.z, s1.w,
                    s2.x, s2.y, s2.z, s2.w, s3.x, s3.y, s3.z, s3.w};
#pragma unroll
    for (int e = 0; e < 8; e++) {
        int k = 256 + e;
        Asw[k * MTILE + (pl ^ swz(k))] = ev[e];
    }
#pragma unroll
    for (int f = 0; f < 16; f++) {
        int k = 264 + f;
        Asw[k * MTILE + (pl ^ swz(k))] = sv[f];
    }
}

// ---------------- kernel 2: persistent fused gather||GEMM pipeline ----------------
__global__ __launch_bounds__(THREADS, 1)
void fused_kernel(const float* __restrict__ node_embs,
                  const int*   __restrict__ path_nodes,
                  const int*   __restrict__ path_lens,
                  const float* __restrict__ edge_feats,
                  const float* __restrict__ scalar_feats,
                  const float* __restrict__ W2,
                  const float* __restrict__ b2,
                  float*       __restrict__ out) {
    extern __shared__ float sm[];
    float* As  = sm;                           // [2][KDIM][64]   147456 B
    float* Bs  = As + 2 * KDIM * MTILE;        // [2][8][256]      16384 B
    float* cs  = Bs + 2 * 8 * H;               // [256]
    float* w2s = cs + H;                       // [256]
    float* qp  = w2s + H;                      // [64][33]          8448 B
    __shared__ int s_nxt;

    int t = threadIdx.x;
    int w = t >> 5, lane = t & 31;

    // constants
    if (t < H) {
        float cv = 0.f;
#pragma unroll
        for (int b = 0; b < 8; b++) cv += g_cpart[b][t];
        cs[t]  = cv;
        w2s[t] = W2[t];
    }
    // zero-pad rows (k = 280..287) once, both buffers
    if (t < MTILE) {
#pragma unroll
        for (int z = 0; z < 8; z++) {
            int k = 280 + z;
            As[k * MTILE + (t ^ swz(k))] = 0.f;
            As[KDIM * MTILE + k * MTILE + (t ^ swz(k))] = 0.f;
        }
    }

    // ---- prologue: gather first tile (static assignment cur = blockIdx.x) ----
    int cur = blockIdx.x;
#pragma unroll 1
    for (int pi = 0; pi < 4; pi++)
        gather_path(As, node_embs, path_nodes, path_lens,
                    cur * MTILE + 4 * w + pi, 4 * w + pi, lane);
    if (t < MTILE)
        edge_rows(As, edge_feats, scalar_feats, cur * MTILE + t, t);

    if (t == 0) s_nxt = atomicAdd(&g_ticket, 1);

    // B stage 0
    const float4* Wf4 = (const float4*)g_Wf;
    float4* Bs4 = (float4*)Bs;
    Bs4[t] = Wf4[t];
    __syncthreads();
    int nxt = s_nxt;
    int buf = 0;

    // GEMM thread mapping: warp tile 16x64, thread tile 4x8
    int wr = w & 3, wc = w >> 2;
    int row = 16 * wr + 4 * (lane & 3);        // 0..60
    int col = 64 * wc + 8 * (lane >> 2);       // 0..248
    int gw = w >> 1;                           // gather stage slot 0..7 (distinct per SMSP)

    while (true) {
        bool hasNext = (nxt < NT);
        const float* Asr = As + buf * (KDIM * MTILE);
        float*       Asw = As + (buf ^ 1) * (KDIM * MTILE);

        u64 acc[4][4];
#pragma unroll
        for (int i = 0; i < 4; i++)
#pragma unroll
            for (int j = 0; j < 4; j++) acc[i][j] = 0ull;

#pragma unroll 1
        for (int s = 0; s < NSTAGES; s++) {
            bool pf = (s + 1 < NSTAGES);
            float4 pb;
            if (pf) pb = Wf4[(s + 1) * 512 + t];

            // interleaved gather of next tile: at most 2 warps per stage, on distinct SMSPs
            if (hasNext) {
                int m = s % 9;
                if (m == gw) {
                    int pi = s / 9;
                    gather_path(Asw, node_embs, path_nodes, path_lens,
                                nxt * MTILE + 4 * w + pi, 4 * w + pi, lane);
                }
                if (s == 8 && t < MTILE)
                    edge_rows(Asw, edge_feats, scalar_feats, nxt * MTILE + t, t);
            }

            const float* Bbuf = Bs + (s & 1) * (8 * H);
            int rowx = row ^ ((s & 7) << 2);
            const float* Ap = Asr + (s * 8) * MTILE;
#pragma unroll
            for (int kk = 0; kk < 8; kk++) {
                float4 a = *(const float4*)(Ap + kk * MTILE + rowx);
                ulonglong2 bA = *(const ulonglong2*)(Bbuf + kk * H + col);
                ulonglong2 bB = *(const ulonglong2*)(Bbuf + kk * H + col + 4);
                float av[4] = {a.x, a.y, a.z, a.w};
#pragma unroll
                for (int i = 0; i < 4; i++) {
                    u64 ad = pack2(av[i], av[i]);
                    ffma2(acc[i][0], ad, bA.x);
                    ffma2(acc[i][1], ad, bA.y);
                    ffma2(acc[i][2], ad, bB.x);
                    ffma2(acc[i][3], ad, bB.y);
                }
            }
            if (pf) {
                Bs4[((s + 1) & 1) * 512 + t] = pb;
                __syncthreads();
            }
        }

        // ---- epilogue: +c, relu, dot(W2) partials ----
        int cgrp = col >> 3;   // 0..31, (row+i, cgrp) uniquely owned
#pragma unroll
        for (int i = 0; i < 4; i++) {
            float si = 0.f;
#pragma unroll
            for (int j = 0; j < 4; j++) {
                float v0, v1;
                unpack2(acc[i][j], v0, v1);
                int jg = col + 2 * j;
                v0 = fmaxf(v0 + cs[jg],     0.f);
                v1 = fmaxf(v1 + cs[jg + 1], 0.f);
                si = fmaf(v0, w2s[jg],     si);
                si = fmaf(v1, w2s[jg + 1], si);
            }
            qp[(row + i) * 33 + cgrp] = si;
        }
        __syncthreads();

        if (t < MTILE) {
            int p = cur * MTILE + t;
            float sv = b2[0];
#pragma unroll
            for (int j = 0; j < 32; j++) sv += qp[t * 33 + j];
            out[p] = (path_lens[p] > 0) ? sv : 0.f;
        }

        if (!hasNext) break;
        cur = nxt; buf ^= 1;
        if (t == 0) s_nxt = atomicAdd(&g_ticket, 1);
        Bs4[t] = Wf4[t];       // B stage 0 of next tile
        __syncthreads();
        nxt = s_nxt;
    }
}

// ---------------- launch ----------------
#define FUSED_SMEM ((2 * KDIM * MTILE + 2 * 8 * H + H + H + 64 * 33) * (int)sizeof(float))

extern "C" void kernel_launch(void* const* d_in, const int* in_sizes, int n_in,
                              void* d_out, int out_size) {
    const float* node_embs    = (const float*)d_in[0];
    const int*   path_nodes   = (const int*)  d_in[1];
    const int*   path_lens    = (const int*)  d_in[2];
    const float* edge_feats   = (const float*)d_in[3];
    const float* scalar_feats = (const float*)d_in[4];
    const float* W1           = (const float*)d_in[5];
    const float* b1           = (const float*)d_in[6];
    const float* W2           = (const float*)d_in[7];
    const float* b2           = (const float*)d_in[8];
    const int*   src_idx      = (const int*)  d_in[9];
    const int*   dst_idx      = (const int*)  d_in[10];
    float* out = (float*)d_out;

    cudaFuncSetAttribute(fused_kernel,
                         cudaFuncAttributeMaxDynamicSharedMemorySize, FUSED_SMEM);

    prep_kernel<<<KDIM + 8, H>>>(W1, node_embs, b1, src_idx, dst_idx);
    fused_kernel<<<GRID, THREADS, FUSED_SMEM>>>(
        node_embs, path_nodes, path_lens, edge_feats, scalar_feats, W2, b2, out);
}

// round 9
// speedup vs baseline: 1.4494x; 1.4494x over previous
#include <cuda_runtime.h>

#define H 256
#define P_PATHS 32768
#define LMAX 16
#define KDIM 288            // 256 path_emb + 8 edge + 16 scalar + 8 zero pad
#define NSTAGES 36          // KDIM / 8
#define MTILE 32            // paths per tile
#define NCOLS 128           // output cols per block (half of H)
#define HALF_TILES (P_PATHS / MTILE)   // 1024 tiles per half
#define GRID 152
#define THREADS 256

// ---------------- persistent scratch (no allocations allowed) ----------------
__device__ __align__(128) float g_Wf[KDIM * H];     // packed W1 tail (k-major, zero-padded)
__device__ __align__(128) float g_cpart[8][H];      // partial src/dst + b1 contribution
__device__ int g_ticket2[2];                        // per-half dynamic tile tickets

// ---------------- packed f32x2 helpers (sm_103a FFMA2 path) ----------------
typedef unsigned long long u64;
__device__ __forceinline__ u64 pack2(float x, float y) {
    u64 r; asm("mov.b64 %0, {%1, %2};" : "=l"(r) : "f"(x), "f"(y)); return r;
}
__device__ __forceinline__ void unpack2(u64 v, float& x, float& y) {
    asm("mov.b64 {%0, %1}, %2;" : "=f"(x), "=f"(y) : "l"(v));
}
__device__ __forceinline__ void ffma2(u64& d, u64 a, u64 b) {
    asm("fma.rn.f32x2 %0, %1, %2, %0;" : "+l"(d) : "l"(a), "l"(b));
}

// bank swizzle for the k-major A tile (32-float rows): permute 4-col groups per 8-k block
__device__ __forceinline__ int swz(int k) { return ((k >> 3) & 7) << 2; }

// ---------------- kernel 1: prep = pack Wf + c partials + ticket reset + out zero ----------------
// fused layout: [src 0:256 | dst 256:512 | path_emb 512:768 | edge 768:776 | scalar 776:792]
__global__ void prep_kernel(const float* __restrict__ W1,
                            const float* __restrict__ node_embs,
                            const float* __restrict__ b1,
                            const int* __restrict__ src_idx,
                            const int* __restrict__ dst_idx,
                            float* __restrict__ out) {
    int bid = blockIdx.x;
    int j = threadIdx.x;     // 0..255
    if (bid == 0 && j < 2) g_ticket2[j] = 0;
    if (bid < KDIM) {
        int k = bid;
        float v = 0.f;
        if (k < 256)       v = W1[(512 + k) * H + j];
        else if (k < 264)  v = W1[(768 + (k - 256)) * H + j];
        else if (k < 280)  v = W1[(776 + (k - 264)) * H + j];
        g_Wf[k * H + j] = v;
    } else if (bid < KDIM + 8) {
        int b = bid - KDIM;  // 0..7 : k slice [b*32, b*32+32)
        const float* s = node_embs + (long)(*src_idx) * H;
        const float* d = node_embs + (long)(*dst_idx) * H;
        float acc = (b == 0) ? b1[j] : 0.f;
        int k0 = b * 32;
#pragma unroll 8
        for (int k = k0; k < k0 + 32; k++) {
            acc = fmaf(s[k], W1[k * H + j], acc);
            acc = fmaf(d[k], W1[(256 + k) * H + j], acc);
        }
        g_cpart[b][j] = acc;
    } else {
        out[(bid - (KDIM + 8)) * 256 + j] = 0.f;   // 128 blocks x 256 = 32768
    }
}

// ---------------- gather: one path mean, warp-collective ----------------
__device__ __forceinline__ void gather_path(float* __restrict__ Asw,
                                            const float* __restrict__ node_embs,
                                            const int* __restrict__ path_nodes,
                                            const int* __restrict__ path_lens,
                                            int p, int pl, int lane) {
    int len = path_lens[p];
    const int4* nb = (const int4*)(path_nodes + (size_t)p * LMAX);
    int4 q0 = nb[0], q1 = nb[1], q2 = nb[2], q3 = nb[3];
    int ids[16] = {q0.x, q0.y, q0.z, q0.w, q1.x, q1.y, q1.z, q1.w,
                   q2.x, q2.y, q2.z, q2.w, q3.x, q3.y, q3.z, q3.w};
    float4 a0 = make_float4(0.f, 0.f, 0.f, 0.f);
    float4 a1 = make_float4(0.f, 0.f, 0.f, 0.f);
#pragma unroll
    for (int l = 0; l < LMAX; l++) {
        if (l < len) {
            const float4* r = (const float4*)(node_embs + (size_t)ids[l] * H);
            float4 v0 = r[lane];
            float4 v1 = r[32 + lane];
            a0.x += v0.x; a0.y += v0.y; a0.z += v0.z; a0.w += v0.w;
            a1.x += v1.x; a1.y += v1.y; a1.z += v1.z; a1.w += v1.w;
        }
    }
    float inv = 1.f / (float)max(len, 1);
    int k0 = 4 * lane;
    float va0[4] = {a0.x, a0.y, a0.z, a0.w};
    float va1[4] = {a1.x, a1.y, a1.z, a1.w};
#pragma unroll
    for (int j = 0; j < 4; j++) {
        int ka = k0 + j, kb = 128 + k0 + j;
        Asw[ka * MTILE + (pl ^ swz(ka))] = va0[j] * inv;
        Asw[kb * MTILE + (pl ^ swz(kb))] = va1[j] * inv;
    }
}

// edge + scalar rows (k = 256..279) for one path, one thread
__device__ __forceinline__ void edge_rows(float* __restrict__ Asw,
                                          const float* __restrict__ edge_feats,
                                          const float* __restrict__ scalar_feats,
                                          int p, int pl) {
    const float4* ef = (const float4*)(edge_feats + (size_t)p * 8);
    float4 e0 = ef[0], e1 = ef[1];
    const float4* sf = (const float4*)(scalar_feats + (size_t)p * 16);
    float4 s0 = sf[0], s1 = sf[1], s2 = sf[2], s3 = sf[3];
    float ev[8]  = {e0.x, e0.y, e0.z, e0.w, e1.x, e1.y, e1.z, e1.w};
    float sv[16] = {s0.x, s0.y, s0.z, s0.w, s1.x, s1.y, s1.z, s1.w,
                    s2.x, s2.y, s2.z, s2.w, s3.x, s3.y, s3.z, s3.w};
#pragma unroll
    for (int e = 0; e < 8; e++) {
        int k = 256 + e;
        Asw[k * MTILE + (pl ^ swz(k))] = ev[e];
    }
#pragma unroll
    for (int f = 0; f < 16; f++) {
        int k = 264 + f;
        Asw[k * MTILE + (pl ^ swz(k))] = sv[f];
    }
}

// ---------------- barrier-free inner GEMM over one tile (B resident in smem) ----------------
__device__ __forceinline__ void gemm_tile(const float* __restrict__ Asr,
                                          const float* __restrict__ Bsm,
                                          int grow, int gcol, u64 (&acc)[4][2]) {
#pragma unroll 1
    for (int k8 = 0; k8 < NSTAGES; k8++) {
        int sw = (k8 & 7) << 2;
        const float* Ap = Asr + k8 * 8 * MTILE + (grow ^ sw);
        const float* Bp = Bsm + k8 * 8 * NCOLS + gcol;
#pragma unroll
        for (int kk = 0; kk < 8; kk++) {
            float4 a = *(const float4*)(Ap + kk * MTILE);
            ulonglong2 b = *(const ulonglong2*)(Bp + kk * NCOLS);
            float av[4] = {a.x, a.y, a.z, a.w};
#pragma unroll
            for (int i = 0; i < 4; i++) {
                u64 ad = pack2(av[i], av[i]);
                ffma2(acc[i][0], ad, b.x);
                ffma2(acc[i][1], ad, b.y);
            }
        }
    }
}

// ---------------- kernel 2: persistent, N-split, barrier-free-mainloop pipeline ----------------
__global__ __launch_bounds__(THREADS, 1)
void fused_kernel(const float* __restrict__ node_embs,
                  const int*   __restrict__ path_nodes,
                  const int*   __restrict__ path_lens,
                  const float* __restrict__ edge_feats,
                  const float* __restrict__ scalar_feats,
                  const float* __restrict__ W2,
                  const float* __restrict__ b2,
                  float*       __restrict__ out) {
    extern __shared__ float sm[];
    float* Bsm = sm;                           // [KDIM][128]      147456 B (this half's W1)
    float* As  = Bsm + KDIM * NCOLS;           // [2][KDIM][32]     73728 B
    float* cs  = As + 2 * KDIM * MTILE;        // [128]
    float* w2s = cs + NCOLS;                   // [128]
    float* qp  = w2s + NCOLS;                  // [32][33]           4224 B
    __shared__ int s_nxt[2];

    int t = threadIdx.x;
    int w = t >> 5, lane = t & 31;
    int half = blockIdx.x & 1;

    if (t == 0) s_nxt[0] = atomicAdd(&g_ticket2[half], 1);

    // B resident load: 288 rows x 128 cols of this half
    {
        const float4* src = (const float4*)g_Wf;
        float4* dst = (float4*)Bsm;
#pragma unroll 4
        for (int i = t; i < KDIM * NCOLS / 4; i += THREADS) {
            int k = i >> 5, j4 = i & 31;       // 32 float4 per row
            dst[i] = src[k * 64 + half * 32 + j4];
        }
    }
    // constants for this half
    if (t < NCOLS) {
        float cv = 0.f;
#pragma unroll
        for (int b = 0; b < 8; b++) cv += g_cpart[b][half * NCOLS + t];
        cs[t]  = cv;
        w2s[t] = W2[half * NCOLS + t];
    }
    // zero-pad rows (k = 280..287), both buffers
    if (t < MTILE) {
#pragma unroll
        for (int z = 0; z < 8; z++) {
            int k = 280 + z;
            As[k * MTILE + (t ^ swz(k))] = 0.f;
            As[KDIM * MTILE + k * MTILE + (t ^ swz(k))] = 0.f;
        }
    }
    __syncthreads();

    int cur = s_nxt[0];
    if (cur >= HALF_TILES) return;             // late-scheduled block: nothing left

    // prologue: gather first tile into buf 0
#pragma unroll 1
    for (int pi = 0; pi < 4; pi++)
        gather_path(As, node_embs, path_nodes, path_lens,
                    cur * MTILE + 4 * w + pi, 4 * w + pi, lane);
    if (t < MTILE)
        edge_rows(As, edge_feats, scalar_feats, cur * MTILE + t, t);
    if (t == 0) s_nxt[1] = atomicAdd(&g_ticket2[half], 1);
    __syncthreads();

    // GEMM thread mapping: 8 warps over 32x128, warp tile 16x32, thread tile 4x4
    int grow = 16 * (w & 1) + 4 * (lane >> 3);   // 0..28
    int gcol = 32 * (w >> 1) + 4 * (lane & 7);   // 0..124
    int cg   = gcol >> 2;                        // 0..31

    int buf = 0;
    while (true) {
        int nxt = s_nxt[buf ^ 1];
        bool hasNext = (nxt < HALF_TILES);
        if (hasNext && t == 0) s_nxt[buf] = atomicAdd(&g_ticket2[half], 1);

        const float* Asr = As + buf * (KDIM * MTILE);
        float*       Asw = As + (buf ^ 1) * (KDIM * MTILE);

        u64 acc[4][2];
#pragma unroll
        for (int i = 0; i < 4; i++) { acc[i][0] = 0ull; acc[i][1] = 0ull; }

        if (w < 4) {
            if (hasNext) {
#pragma unroll 1
                for (int pi = 0; pi < 4; pi++)
                    gather_path(Asw, node_embs, path_nodes, path_lens,
                                nxt * MTILE + 4 * w + pi, 4 * w + pi, lane);
                if (t < MTILE)
                    edge_rows(Asw, edge_feats, scalar_feats, nxt * MTILE + t, t);
            }
            gemm_tile(Asr, Bsm, grow, gcol, acc);
        } else {
            gemm_tile(Asr, Bsm, grow, gcol, acc);
            if (hasNext) {
#pragma unroll 1
                for (int pi = 0; pi < 4; pi++)
                    gather_path(Asw, node_embs, path_nodes, path_lens,
                                nxt * MTILE + 4 * w + pi, 4 * w + pi, lane);
            }
        }

        // epilogue: +c, relu, dot(W2) partials
#pragma unroll
        for (int i = 0; i < 4; i++) {
            float v0, v1, v2, v3;
            unpack2(acc[i][0], v0, v1);
            unpack2(acc[i][1], v2, v3);
            v0 = fmaxf(v0 + cs[gcol],     0.f);
            v1 = fmaxf(v1 + cs[gcol + 1], 0.f);
            v2 = fmaxf(v2 + cs[gcol + 2], 0.f);
            v3 = fmaxf(v3 + cs[gcol + 3], 0.f);
            float si;
            si = v0 * w2s[gcol];
            si = fmaf(v1, w2s[gcol + 1], si);
            si = fmaf(v2, w2s[gcol + 2], si);
            si = fmaf(v3, w2s[gcol + 3], si);
            qp[(grow + i) * 33 + cg] = si;
        }
        __syncthreads();

        if (t < MTILE) {
            int p = cur * MTILE + t;
            float sv = (half == 0) ? b2[0] : 0.f;
#pragma unroll
            for (int j = 0; j < 32; j++) sv += qp[t * 33 + j];
            atomicAdd(&out[p], (path_lens[p] > 0) ? sv : 0.f);
        }

        if (!hasNext) break;
        cur = nxt; buf ^= 1;
        __syncthreads();
    }
}

// ---------------- launch ----------------
#define FUSED_SMEM ((KDIM * NCOLS + 2 * KDIM * MTILE + NCOLS + NCOLS + 32 * 33) * (int)sizeof(float))

extern "C" void kernel_launch(void* const* d_in, const int* in_sizes, int n_in,
                              void* d_out, int out_size) {
    const float* node_embs    = (const float*)d_in[0];
    const int*   path_nodes   = (const int*)  d_in[1];
    const int*   path_lens    = (const int*)  d_in[2];
    const float* edge_feats   = (const float*)d_in[3];
    const float* scalar_feats = (const float*)d_in[4];
    const float* W1           = (const float*)d_in[5];
    const float* b1           = (const float*)d_in[6];
    const float* W2           = (const float*)d_in[7];
    const float* b2           = (const float*)d_in[8];
    const int*   src_idx      = (const int*)  d_in[9];
    const int*   dst_idx      = (const int*)  d_in[10];
    float* out = (float*)d_out;

    cudaFuncSetAttribute(fused_kernel,
                         cudaFuncAttributeMaxDynamicSharedMemorySize, FUSED_SMEM);

    prep_kernel<<<KDIM + 8 + 128, H>>>(W1, node_embs, b1, src_idx, dst_idx, out);
    fused_kernel<<<GRID, THREADS, FUSED_SMEM>>>(
        node_embs, path_nodes, path_lens, edge_feats, scalar_feats, W2, b2, out);
}